// round 2
// baseline (speedup 1.0000x reference)
#include <cuda_runtime.h>

#define NN 65536
#define NE 1048576
#define DIN 1024
#define DH 64
#define NC 32

// ---------------- scratch (static device globals; no allocs) ----------------
__device__ int   g_is64;
__device__ int   g_src[NE];
__device__ int   g_dst[NE];
__device__ int   g_deg[NN];
__device__ int   g_scan[NN];
__device__ int   g_bsum[64];
__device__ int   g_boff[64];
__device__ int   g_rowptr[NN + 1];
__device__ int   g_cursor[NN];
__device__ int   g_col[NE];
__device__ float g_dinv[NN];
__device__ float g_y1[(size_t)NN * DH];
__device__ float g_h [(size_t)NN * DH];
__device__ float g_y2[(size_t)NN * NC];

// packed f32x2 FMA (sm_100+): d = a*b + c elementwise on packed pairs
__device__ __forceinline__ unsigned long long fma2(unsigned long long a,
                                                   unsigned long long b,
                                                   unsigned long long c) {
    unsigned long long d;
    asm("fma.rn.f32x2 %0, %1, %2, %3;" : "=l"(d) : "l"(a), "l"(b), "l"(c));
    return d;
}

// ---------------- dtype detect: int64 edge_index has all-zero odd words ----------------
__global__ void k_detect(const int* __restrict__ w) {
    __shared__ int s[1024];
    int t = threadIdx.x;
    int acc = 0;
    // sample odd words in first 2*65536 ints (512KB) — in bounds for both dtypes
    for (int i = t; i < 65536; i += 1024) acc |= w[2 * i + 1];
    s[t] = acc;
    __syncthreads();
    for (int off = 512; off; off >>= 1) {
        if (t < off) s[t] |= s[t + off];
        __syncthreads();
    }
    if (t == 0) g_is64 = (s[0] == 0) ? 1 : 0;
}

// ---------------- graph preprocessing ----------------
__global__ void k_prep(const int* __restrict__ w) {
    int i = blockIdx.x * blockDim.x + threadIdx.x;
    if (i < NE) {
        int s, d;
        if (g_is64) {  // int64 layout: value in even word
            s = w[2 * i];
            d = w[2 * (NE + i)];
        } else {       // int32 layout
            s = w[i];
            d = w[NE + i];
        }
        g_src[i] = s & (NN - 1);
        g_dst[i] = d & (NN - 1);
    }
    if (i < NN) g_deg[i] = 0;
}

__global__ void k_count() {
    int i = blockIdx.x * blockDim.x + threadIdx.x;
    if (i < NE) atomicAdd(&g_deg[g_dst[i]], 1);
}

__global__ void k_scan1() {  // 64 blocks x 1024: per-block inclusive scan
    __shared__ int s[1024];
    int t = threadIdx.x;
    int gid = blockIdx.x * 1024 + t;
    s[t] = g_deg[gid];
    __syncthreads();
    for (int off = 1; off < 1024; off <<= 1) {
        int v = (t >= off) ? s[t - off] : 0;
        __syncthreads();
        s[t] += v;
        __syncthreads();
    }
    g_scan[gid] = s[t];
    if (t == 1023) g_bsum[blockIdx.x] = s[t];
}

__global__ void k_scan2() {  // 1 block x 64: scan of block sums -> exclusive offsets
    __shared__ int s[64];
    int t = threadIdx.x;
    s[t] = g_bsum[t];
    __syncthreads();
    for (int off = 1; off < 64; off <<= 1) {
        int v = (t >= off) ? s[t - off] : 0;
        __syncthreads();
        s[t] += v;
        __syncthreads();
    }
    g_boff[t] = s[t] - g_bsum[t];
}

__global__ void k_scan3() {
    int i = blockIdx.x * blockDim.x + threadIdx.x;
    if (i >= NN) return;
    int excl = g_scan[i] - g_deg[i] + g_boff[i >> 10];
    g_rowptr[i] = excl;
    g_cursor[i] = excl;
    g_dinv[i] = rsqrtf((float)g_deg[i] + 1.0f);
    if (i == 0) g_rowptr[NN] = NE;
}

__global__ void k_fill() {
    int e = blockIdx.x * blockDim.x + threadIdx.x;
    if (e < NE) {
        int d = g_dst[e];
        int p = atomicAdd(&g_cursor[d], 1);
        g_col[p] = g_src[e];
    }
}

// ---------------- GEMM1: y1 = dinv[row] * (x @ W1), packed f32x2 ----------------
// block tile 128x64, 128 threads, thread tile 8 rows (4 f32x2 pairs) x 8 cols
#define BM 128
#define BK 32

__global__ __launch_bounds__(128, 4) void k_gemm1(const float* __restrict__ A,
                                                  const float* __restrict__ W) {
    __shared__ float  As[BK][BM + 2];   // k-major transposed; row stride 130 floats (8B-aligned)
    __shared__ float2 Ws[BK][DH];       // W duplicated into both halves of float2

    int tid = threadIdx.x;
    int blockRow = blockIdx.x * BM;
    int m = tid >> 3;     // 0..15: row group (8 rows)
    int n = tid & 7;      // 0..7 : col lane (cols n, n+8, ..., n+56)

    unsigned long long acc[4][8];
#pragma unroll
    for (int p = 0; p < 4; p++)
#pragma unroll
        for (int j = 0; j < 8; j++) acc[p][j] = 0ull;

    for (int kt = 0; kt < DIN; kt += BK) {
        // stage A tile (128 rows x 32 k) as float4, store transposed
#pragma unroll
        for (int i = 0; i < 8; i++) {
            int f = tid + i * 128;          // 0..1023 float4 id
            int row = f >> 3;
            int kq = (f & 7) * 4;
            float4 v = *(const float4*)(A + (size_t)(blockRow + row) * DIN + kt + kq);
            As[kq + 0][row] = v.x;
            As[kq + 1][row] = v.y;
            As[kq + 2][row] = v.z;
            As[kq + 3][row] = v.w;
        }
        // stage W tile (32 k x 64 cols), duplicated
#pragma unroll
        for (int i = 0; i < 16; i++) {
            int f = tid + i * 128;          // 0..2047
            int k = f >> 6, c = f & 63;
            float w = W[(size_t)(kt + k) * DH + c];
            Ws[k][c] = make_float2(w, w);
        }
        __syncthreads();

#pragma unroll
        for (int k = 0; k < BK; k++) {
            unsigned long long a[4], b[8];
#pragma unroll
            for (int p = 0; p < 4; p++)
                a[p] = *(const unsigned long long*)&As[k][m * 8 + 2 * p];
#pragma unroll
            for (int j = 0; j < 8; j++)
                b[j] = *(const unsigned long long*)&Ws[k][n + 8 * j];
#pragma unroll
            for (int p = 0; p < 4; p++)
#pragma unroll
                for (int j = 0; j < 8; j++)
                    acc[p][j] = fma2(a[p], b[j], acc[p][j]);
        }
        __syncthreads();
    }

#pragma unroll
    for (int p = 0; p < 4; p++) {
        int r0 = blockRow + m * 8 + 2 * p;
        float d0 = g_dinv[r0];
        float d1 = g_dinv[r0 + 1];
#pragma unroll
        for (int j = 0; j < 8; j++) {
            float2 v = *(float2*)&acc[p][j];
            g_y1[(size_t)r0 * DH + n + 8 * j]       = v.x * d0;
            g_y1[(size_t)(r0 + 1) * DH + n + 8 * j] = v.y * d1;
        }
    }
}

// ---------------- layer-1 aggregation + bias + relu (warp per node) ----------------
__global__ __launch_bounds__(256) void k_agg1(const float* __restrict__ b1) {
    int warp = (blockIdx.x * blockDim.x + threadIdx.x) >> 5;
    int lane = threadIdx.x & 31;
    if (warp >= NN) return;
    const float* yi = g_y1 + (size_t)warp * DH;
    float a0 = yi[lane];
    float a1 = yi[lane + 32];
    int e = g_rowptr[warp], e1 = g_rowptr[warp + 1];
    for (; e + 4 <= e1; e += 4) {
        int s0 = g_col[e], s1 = g_col[e + 1], s2 = g_col[e + 2], s3 = g_col[e + 3];
        const float* p0 = g_y1 + (size_t)s0 * DH;
        const float* p1 = g_y1 + (size_t)s1 * DH;
        const float* p2 = g_y1 + (size_t)s2 * DH;
        const float* p3 = g_y1 + (size_t)s3 * DH;
        float v00 = p0[lane], v10 = p1[lane], v20 = p2[lane], v30 = p3[lane];
        float v01 = p0[lane + 32], v11 = p1[lane + 32], v21 = p2[lane + 32], v31 = p3[lane + 32];
        a0 += (v00 + v10) + (v20 + v30);
        a1 += (v01 + v11) + (v21 + v31);
    }
    for (; e < e1; e++) {
        int s = g_col[e];
        a0 += g_y1[(size_t)s * DH + lane];
        a1 += g_y1[(size_t)s * DH + lane + 32];
    }
    float dv = g_dinv[warp];
    g_h[(size_t)warp * DH + lane]      = fmaxf(fmaf(dv, a0, b1[lane]), 0.0f);
    g_h[(size_t)warp * DH + lane + 32] = fmaxf(fmaf(dv, a1, b1[lane + 32]), 0.0f);
}

// ---------------- GEMM2: y2 = dinv * (h @ W2)  (warp per node) ----------------
__global__ __launch_bounds__(256) void k_gemm2(const float* __restrict__ W2) {
    __shared__ float Ws[DH * NC];
    for (int i = threadIdx.x; i < DH * NC; i += 256) Ws[i] = W2[i];
    __syncthreads();
    int warp = (blockIdx.x * blockDim.x + threadIdx.x) >> 5;
    int lane = threadIdx.x & 31;
    if (warp >= NN) return;
    const float* hr = g_h + (size_t)warp * DH;
    float acc = 0.0f;
#pragma unroll
    for (int k = 0; k < DH; k += 4) {
        float4 hv = *(const float4*)(hr + k);
        acc = fmaf(hv.x, Ws[(k + 0) * NC + lane], acc);
        acc = fmaf(hv.y, Ws[(k + 1) * NC + lane], acc);
        acc = fmaf(hv.z, Ws[(k + 2) * NC + lane], acc);
        acc = fmaf(hv.w, Ws[(k + 3) * NC + lane], acc);
    }
    g_y2[(size_t)warp * NC + lane] = acc * g_dinv[warp];
}

// ---------------- layer-2 aggregation + bias + log_softmax ----------------
__global__ __launch_bounds__(256) void k_agg2(const float* __restrict__ b2,
                                              float* __restrict__ out) {
    int warp = (blockIdx.x * blockDim.x + threadIdx.x) >> 5;
    int lane = threadIdx.x & 31;
    if (warp >= NN) return;
    float a = g_y2[(size_t)warp * NC + lane];
    int e = g_rowptr[warp], e1 = g_rowptr[warp + 1];
    for (; e + 4 <= e1; e += 4) {
        int s0 = g_col[e], s1 = g_col[e + 1], s2 = g_col[e + 2], s3 = g_col[e + 3];
        float v0 = g_y2[(size_t)s0 * NC + lane];
        float v1 = g_y2[(size_t)s1 * NC + lane];
        float v2 = g_y2[(size_t)s2 * NC + lane];
        float v3 = g_y2[(size_t)s3 * NC + lane];
        a += (v0 + v1) + (v2 + v3);
    }
    for (; e < e1; e++) a += g_y2[(size_t)g_col[e] * NC + lane];

    float v = fmaf(g_dinv[warp], a, b2[lane]);
    // log_softmax over the 32 lanes
    float mx = v;
#pragma unroll
    for (int o = 16; o; o >>= 1) mx = fmaxf(mx, __shfl_xor_sync(0xffffffffu, mx, o));
    float ex = __expf(v - mx);
    float sm = ex;
#pragma unroll
    for (int o = 16; o; o >>= 1) sm += __shfl_xor_sync(0xffffffffu, sm, o);
    out[(size_t)warp * NC + lane] = v - mx - logf(sm);
}

// ---------------- launch ----------------
extern "C" void kernel_launch(void* const* d_in, const int* in_sizes, int n_in,
                              void* d_out, int out_size) {
    const float* x  = (const float*)d_in[0];
    const int*   ei = (const int*)d_in[1];   // int32 view; k_detect handles int64 layout
    const float* W1 = (const float*)d_in[2];
    const float* b1 = (const float*)d_in[3];
    const float* W2 = (const float*)d_in[4];
    const float* b2 = (const float*)d_in[5];
    float* out = (float*)d_out;

    k_detect<<<1, 1024>>>(ei);
    k_prep  <<<(NE + 255) / 256, 256>>>(ei);
    k_count <<<NE / 256, 256>>>();
    k_scan1 <<<64, 1024>>>();
    k_scan2 <<<1, 64>>>();
    k_scan3 <<<NN / 256, 256>>>();
    k_fill  <<<NE / 256, 256>>>();
    k_gemm1 <<<NN / BM, 128>>>(x, W1);
    k_agg1  <<<NN / 8, 256>>>(b1);
    k_gemm2 <<<NN / 8, 256>>>(W2);
    k_agg2  <<<NN / 8, 256>>>(b2, out);
}

// round 3
// speedup vs baseline: 1.5266x; 1.5266x over previous
#include <cuda_runtime.h>
#include <cuda_bf16.h>

#define NN 65536
#define NE 1048576
#define DIN 1024
#define DH 64
#define NC 32

// ---------------- scratch (static device globals; no allocs) ----------------
__device__ int   g_is64;
__device__ int   g_src[NE];
__device__ int   g_dst[NE];
__device__ int   g_deg[NN];
__device__ int   g_scan[NN];
__device__ int   g_bsum[64];
__device__ int   g_boff[64];
__device__ int   g_rowptr[NN + 1];
__device__ int   g_cursor[NN];
__device__ int   g_col[NE];
__device__ float g_dinv[NN];
__device__ float g_y1[(size_t)NN * DH];
__device__ float g_h [(size_t)NN * DH];
__device__ float g_y2[(size_t)NN * NC];
// W1^T in bf16 hi/lo: [DH rows][DIN cols], k-contiguous
__device__ __nv_bfloat16 g_w1hi[DH * DIN];
__device__ __nv_bfloat16 g_w1lo[DH * DIN];

// ---------------- dtype detect: int64 edge_index has all-zero odd words ----------------
__global__ void k_detect(const int* __restrict__ w) {
    __shared__ int s[1024];
    int t = threadIdx.x;
    int acc = 0;
    for (int i = t; i < 65536; i += 1024) acc |= w[2 * i + 1];
    s[t] = acc;
    __syncthreads();
    for (int off = 512; off; off >>= 1) {
        if (t < off) s[t] |= s[t + off];
        __syncthreads();
    }
    if (t == 0) g_is64 = (s[0] == 0) ? 1 : 0;
}

// ---------------- graph preprocessing ----------------
__global__ void k_prep(const int* __restrict__ w) {
    int i = blockIdx.x * blockDim.x + threadIdx.x;
    if (i < NE) {
        int s, d;
        if (g_is64) { s = w[2 * i]; d = w[2 * (NE + i)]; }
        else        { s = w[i];     d = w[NE + i]; }
        g_src[i] = s & (NN - 1);
        g_dst[i] = d & (NN - 1);
    }
    if (i < NN) g_deg[i] = 0;
}

__global__ void k_count() {
    int i = blockIdx.x * blockDim.x + threadIdx.x;
    if (i < NE) atomicAdd(&g_deg[g_dst[i]], 1);
}

__global__ void k_scan1() {
    __shared__ int s[1024];
    int t = threadIdx.x;
    int gid = blockIdx.x * 1024 + t;
    s[t] = g_deg[gid];
    __syncthreads();
    for (int off = 1; off < 1024; off <<= 1) {
        int v = (t >= off) ? s[t - off] : 0;
        __syncthreads();
        s[t] += v;
        __syncthreads();
    }
    g_scan[gid] = s[t];
    if (t == 1023) g_bsum[blockIdx.x] = s[t];
}

__global__ void k_scan2() {
    __shared__ int s[64];
    int t = threadIdx.x;
    s[t] = g_bsum[t];
    __syncthreads();
    for (int off = 1; off < 64; off <<= 1) {
        int v = (t >= off) ? s[t - off] : 0;
        __syncthreads();
        s[t] += v;
        __syncthreads();
    }
    g_boff[t] = s[t] - g_bsum[t];
}

__global__ void k_scan3() {
    int i = blockIdx.x * blockDim.x + threadIdx.x;
    if (i >= NN) return;
    int excl = g_scan[i] - g_deg[i] + g_boff[i >> 10];
    g_rowptr[i] = excl;
    g_cursor[i] = excl;
    g_dinv[i] = rsqrtf((float)g_deg[i] + 1.0f);
    if (i == 0) g_rowptr[NN] = NE;
}

__global__ void k_fill() {
    int e = blockIdx.x * blockDim.x + threadIdx.x;
    if (e < NE) {
        int d = g_dst[e];
        int p = atomicAdd(&g_cursor[d], 1);
        g_col[p] = g_src[e];
    }
}

// ---------------- W1 split-bf16 transpose: Wt[n][k] ----------------
__global__ void k_wconv(const float* __restrict__ W1) {
    int i = blockIdx.x * blockDim.x + threadIdx.x;  // i = k*64+n
    if (i >= DIN * DH) return;
    int k = i >> 6, n = i & 63;
    float w = W1[i];
    __nv_bfloat16 hi = __float2bfloat16_rn(w);
    float r = w - __bfloat162float(hi);
    g_w1hi[n * DIN + k] = hi;
    g_w1lo[n * DIN + k] = __float2bfloat16_rn(r);
}

// ---------------- GEMM1 (tensor cores): y1 = dinv[row] * (x @ W1) ----------------
// CTA: 256 threads (8 warps), tile M=128 x N=64, K-chunk 32.
// warp grid 4(m) x 2(n); per warp: 2 m16-tiles x 4 n8-tiles.
// Split-bf16 3-pass: hi*Whi + hi*Wlo + lo*Whi.
#define SAS 40  // smem row stride in bf16 elems -> conflict-free frag loads

__device__ __forceinline__ void mma16816(float* d, const unsigned* a, const unsigned* b) {
    asm("mma.sync.aligned.m16n8k16.row.col.f32.bf16.bf16.f32 "
        "{%0,%1,%2,%3}, {%4,%5,%6,%7}, {%8,%9}, {%0,%1,%2,%3};"
        : "+f"(d[0]), "+f"(d[1]), "+f"(d[2]), "+f"(d[3])
        : "r"(a[0]), "r"(a[1]), "r"(a[2]), "r"(a[3]), "r"(b[0]), "r"(b[1]));
}

__global__ __launch_bounds__(256, 2) void k_gemm1t(const float* __restrict__ A) {
    __shared__ __nv_bfloat16 Ah[128][SAS], Al[128][SAS];
    __shared__ __nv_bfloat16 Bh[64][SAS],  Bl[64][SAS];

    int tid = threadIdx.x;
    int wid = tid >> 5, lane = tid & 31;
    int wm = wid >> 1, wn = wid & 1;
    int g = lane >> 2, t = lane & 3;
    int blockRow = blockIdx.x * 128;

    float acc[2][4][4];
#pragma unroll
    for (int mt = 0; mt < 2; mt++)
#pragma unroll
        for (int nt = 0; nt < 4; nt++)
#pragma unroll
            for (int q = 0; q < 4; q++) acc[mt][nt][q] = 0.0f;

    const unsigned* w1hi32 = (const unsigned*)g_w1hi;
    const unsigned* w1lo32 = (const unsigned*)g_w1lo;

    // prefetch chunk 0
    float4 av[4];
    unsigned bhv[4], blv[4];
#pragma unroll
    for (int i = 0; i < 4; i++) {
        int f = tid + i * 256;
        int row = f >> 3, kq = (f & 7) * 4;
        av[i] = *(const float4*)(A + (size_t)(blockRow + row) * DIN + kq);
        int br = f >> 4, bc = f & 15;          // Wt row, b32 col within chunk
        bhv[i] = w1hi32[br * (DIN / 2) + bc];
        blv[i] = w1lo32[br * (DIN / 2) + bc];
    }

    for (int kt = 0; kt < DIN; kt += 32) {
        // stage current chunk into smem (convert A to hi/lo bf16)
#pragma unroll
        for (int i = 0; i < 4; i++) {
            int f = tid + i * 256;
            int row = f >> 3, kq = (f & 7) * 4;
            float4 v = av[i];
            __nv_bfloat162 hxy = __float22bfloat162_rn(make_float2(v.x, v.y));
            __nv_bfloat162 hzw = __float22bfloat162_rn(make_float2(v.z, v.w));
            float rx = v.x - __bfloat162float(__low2bfloat16(hxy));
            float ry = v.y - __bfloat162float(__high2bfloat16(hxy));
            float rz = v.z - __bfloat162float(__low2bfloat16(hzw));
            float rw = v.w - __bfloat162float(__high2bfloat16(hzw));
            __nv_bfloat162 lxy = __float22bfloat162_rn(make_float2(rx, ry));
            __nv_bfloat162 lzw = __float22bfloat162_rn(make_float2(rz, rw));
            *(unsigned*)&Ah[row][kq]     = *(unsigned*)&hxy;
            *(unsigned*)&Ah[row][kq + 2] = *(unsigned*)&hzw;
            *(unsigned*)&Al[row][kq]     = *(unsigned*)&lxy;
            *(unsigned*)&Al[row][kq + 2] = *(unsigned*)&lzw;
            int br = f >> 4, bc = f & 15;
            *(unsigned*)&Bh[br][bc * 2] = bhv[i];
            *(unsigned*)&Bl[br][bc * 2] = blv[i];
        }
        __syncthreads();

        // prefetch next chunk
        if (kt + 32 < DIN) {
#pragma unroll
            for (int i = 0; i < 4; i++) {
                int f = tid + i * 256;
                int row = f >> 3, kq = (f & 7) * 4;
                av[i] = *(const float4*)(A + (size_t)(blockRow + row) * DIN + kt + 32 + kq);
                int br = f >> 4, bc = f & 15;
                bhv[i] = w1hi32[br * (DIN / 2) + (kt + 32) / 2 + bc];
                blv[i] = w1lo32[br * (DIN / 2) + (kt + 32) / 2 + bc];
            }
        }

#pragma unroll
        for (int kk = 0; kk < 32; kk += 16) {
            unsigned ah[2][4], al[2][4], bh[4][2], bl[4][2];
#pragma unroll
            for (int mt = 0; mt < 2; mt++) {
                int r0 = wm * 32 + mt * 16;
                ah[mt][0] = *(unsigned*)&Ah[r0 + g][kk + 2 * t];
                ah[mt][1] = *(unsigned*)&Ah[r0 + g + 8][kk + 2 * t];
                ah[mt][2] = *(unsigned*)&Ah[r0 + g][kk + 2 * t + 8];
                ah[mt][3] = *(unsigned*)&Ah[r0 + g + 8][kk + 2 * t + 8];
                al[mt][0] = *(unsigned*)&Al[r0 + g][kk + 2 * t];
                al[mt][1] = *(unsigned*)&Al[r0 + g + 8][kk + 2 * t];
                al[mt][2] = *(unsigned*)&Al[r0 + g][kk + 2 * t + 8];
                al[mt][3] = *(unsigned*)&Al[r0 + g + 8][kk + 2 * t + 8];
            }
#pragma unroll
            for (int nt = 0; nt < 4; nt++) {
                int c0 = wn * 32 + nt * 8;
                bh[nt][0] = *(unsigned*)&Bh[c0 + g][kk + 2 * t];
                bh[nt][1] = *(unsigned*)&Bh[c0 + g][kk + 2 * t + 8];
                bl[nt][0] = *(unsigned*)&Bl[c0 + g][kk + 2 * t];
                bl[nt][1] = *(unsigned*)&Bl[c0 + g][kk + 2 * t + 8];
            }
#pragma unroll
            for (int mt = 0; mt < 2; mt++)
#pragma unroll
                for (int nt = 0; nt < 4; nt++) {
                    mma16816(acc[mt][nt], ah[mt], bh[nt]);
                    mma16816(acc[mt][nt], ah[mt], bl[nt]);
                    mma16816(acc[mt][nt], al[mt], bh[nt]);
                }
        }
        __syncthreads();
    }

    // epilogue: scale by dinv[row], store
#pragma unroll
    for (int mt = 0; mt < 2; mt++) {
        int r0 = blockRow + wm * 32 + mt * 16 + g;
        int r1 = r0 + 8;
        float d0 = g_dinv[r0], d1 = g_dinv[r1];
#pragma unroll
        for (int nt = 0; nt < 4; nt++) {
            int c = wn * 32 + nt * 8 + 2 * t;
            g_y1[(size_t)r0 * DH + c]     = acc[mt][nt][0] * d0;
            g_y1[(size_t)r0 * DH + c + 1] = acc[mt][nt][1] * d0;
            g_y1[(size_t)r1 * DH + c]     = acc[mt][nt][2] * d1;
            g_y1[(size_t)r1 * DH + c + 1] = acc[mt][nt][3] * d1;
        }
    }
}

// ---------------- layer-1 aggregation + bias + relu (warp per node) ----------------
__global__ __launch_bounds__(256) void k_agg1(const float* __restrict__ b1) {
    int warp = (blockIdx.x * blockDim.x + threadIdx.x) >> 5;
    int lane = threadIdx.x & 31;
    if (warp >= NN) return;
    const float* yi = g_y1 + (size_t)warp * DH;
    float a0 = yi[lane];
    float a1 = yi[lane + 32];
    int e = g_rowptr[warp], e1 = g_rowptr[warp + 1];
    for (; e + 4 <= e1; e += 4) {
        int s0 = g_col[e], s1 = g_col[e + 1], s2 = g_col[e + 2], s3 = g_col[e + 3];
        const float* p0 = g_y1 + (size_t)s0 * DH;
        const float* p1 = g_y1 + (size_t)s1 * DH;
        const float* p2 = g_y1 + (size_t)s2 * DH;
        const float* p3 = g_y1 + (size_t)s3 * DH;
        float v00 = p0[lane], v10 = p1[lane], v20 = p2[lane], v30 = p3[lane];
        float v01 = p0[lane + 32], v11 = p1[lane + 32], v21 = p2[lane + 32], v31 = p3[lane + 32];
        a0 += (v00 + v10) + (v20 + v30);
        a1 += (v01 + v11) + (v21 + v31);
    }
    for (; e < e1; e++) {
        int s = g_col[e];
        a0 += g_y1[(size_t)s * DH + lane];
        a1 += g_y1[(size_t)s * DH + lane + 32];
    }
    float dv = g_dinv[warp];
    g_h[(size_t)warp * DH + lane]      = fmaxf(fmaf(dv, a0, b1[lane]), 0.0f);
    g_h[(size_t)warp * DH + lane + 32] = fmaxf(fmaf(dv, a1, b1[lane + 32]), 0.0f);
}

// ---------------- GEMM2: y2 = dinv * (h @ W2)  (warp per node) ----------------
__global__ __launch_bounds__(256) void k_gemm2(const float* __restrict__ W2) {
    __shared__ float Ws[DH * NC];
    for (int i = threadIdx.x; i < DH * NC; i += 256) Ws[i] = W2[i];
    __syncthreads();
    int warp = (blockIdx.x * blockDim.x + threadIdx.x) >> 5;
    int lane = threadIdx.x & 31;
    if (warp >= NN) return;
    const float* hr = g_h + (size_t)warp * DH;
    float acc = 0.0f;
#pragma unroll
    for (int k = 0; k < DH; k += 4) {
        float4 hv = *(const float4*)(hr + k);
        acc = fmaf(hv.x, Ws[(k + 0) * NC + lane], acc);
        acc = fmaf(hv.y, Ws[(k + 1) * NC + lane], acc);
        acc = fmaf(hv.z, Ws[(k + 2) * NC + lane], acc);
        acc = fmaf(hv.w, Ws[(k + 3) * NC + lane], acc);
    }
    g_y2[(size_t)warp * NC + lane] = acc * g_dinv[warp];
}

// ---------------- layer-2 aggregation + bias + log_softmax ----------------
__global__ __launch_bounds__(256) void k_agg2(const float* __restrict__ b2,
                                              float* __restrict__ out) {
    int warp = (blockIdx.x * blockDim.x + threadIdx.x) >> 5;
    int lane = threadIdx.x & 31;
    if (warp >= NN) return;
    float a = g_y2[(size_t)warp * NC + lane];
    int e = g_rowptr[warp], e1 = g_rowptr[warp + 1];
    for (; e + 4 <= e1; e += 4) {
        int s0 = g_col[e], s1 = g_col[e + 1], s2 = g_col[e + 2], s3 = g_col[e + 3];
        float v0 = g_y2[(size_t)s0 * NC + lane];
        float v1 = g_y2[(size_t)s1 * NC + lane];
        float v2 = g_y2[(size_t)s2 * NC + lane];
        float v3 = g_y2[(size_t)s3 * NC + lane];
        a += (v0 + v1) + (v2 + v3);
    }
    for (; e < e1; e++) a += g_y2[(size_t)g_col[e] * NC + lane];

    float v = fmaf(g_dinv[warp], a, b2[lane]);
    float mx = v;
#pragma unroll
    for (int o = 16; o; o >>= 1) mx = fmaxf(mx, __shfl_xor_sync(0xffffffffu, mx, o));
    float ex = __expf(v - mx);
    float sm = ex;
#pragma unroll
    for (int o = 16; o; o >>= 1) sm += __shfl_xor_sync(0xffffffffu, sm, o);
    out[(size_t)warp * NC + lane] = v - mx - logf(sm);
}

// ---------------- launch ----------------
extern "C" void kernel_launch(void* const* d_in, const int* in_sizes, int n_in,
                              void* d_out, int out_size) {
    const float* x  = (const float*)d_in[0];
    const int*   ei = (const int*)d_in[1];
    const float* W1 = (const float*)d_in[2];
    const float* b1 = (const float*)d_in[3];
    const float* W2 = (const float*)d_in[4];
    const float* b2 = (const float*)d_in[5];
    float* out = (float*)d_out;

    k_detect<<<1, 1024>>>(ei);
    k_prep  <<<(NE + 255) / 256, 256>>>(ei);
    k_count <<<NE / 256, 256>>>();
    k_scan1 <<<64, 1024>>>();
    k_scan2 <<<1, 64>>>();
    k_scan3 <<<NN / 256, 256>>>();
    k_fill  <<<NE / 256, 256>>>();
    k_wconv <<<(DIN * DH + 255) / 256, 256>>>(W1);
    k_gemm1t<<<NN / 128, 256>>>(x);
    k_agg1  <<<NN / 8, 256>>>(b1);
    k_gemm2 <<<NN / 8, 256>>>(W2);
    k_agg2  <<<NN / 8, 256>>>(b2, out);
}

// round 5
// speedup vs baseline: 1.6734x; 1.0962x over previous
#include <cuda_runtime.h>
#include <cuda_fp16.h>

#define NN 65536
#define NE 1048576
#define DIN 1024
#define DH 64
#define NC 32

// ---------------- scratch (static device globals; no allocs) ----------------
__device__ int    g_is64;
__device__ int    g_tile;
__device__ int    g_deg[NN];
__device__ int    g_scan[NN];
__device__ int    g_bsum[64];
__device__ int    g_boff[64];
__device__ int    g_rowptr[NN + 1];
__device__ int    g_cursor[NN];
__device__ int    g_col[NE];
__device__ float  g_dinv[NN];
__device__ float  g_y1[(size_t)NN * DH];
__device__ float  g_h [(size_t)NN * DH];
__device__ float  g_y2[(size_t)NN * NC];
__device__ __half g_w1h[DH * DIN];   // W1^T in fp16: [n][k], k-contiguous

// ---------------- dtype detect + zero deg ----------------
__global__ void k_detect(const int* __restrict__ w) {
    __shared__ int s[1024];
    int t = threadIdx.x;
    int acc = 0;
    for (int i = t; i < 65536; i += 1024) acc |= w[2 * i + 1];
    s[t] = acc;
    for (int i = t; i < NN; i += 1024) g_deg[i] = 0;
    __syncthreads();
    for (int off = 512; off; off >>= 1) {
        if (t < off) s[t] |= s[t + off];
        __syncthreads();
    }
    if (t == 0) g_is64 = (s[0] == 0) ? 1 : 0;
}

// ---------------- degree count straight from edge_index ----------------
__global__ void k_prep(const int* __restrict__ w) {
    int i = blockIdx.x * blockDim.x + threadIdx.x;
    if (i >= NE) return;
    int d = g_is64 ? w[2 * (NE + i)] : w[NE + i];
    atomicAdd(&g_deg[d & (NN - 1)], 1);
}

__global__ void k_scan1() {
    __shared__ int s[1024];
    int t = threadIdx.x;
    int gid = blockIdx.x * 1024 + t;
    s[t] = g_deg[gid];
    __syncthreads();
    for (int off = 1; off < 1024; off <<= 1) {
        int v = (t >= off) ? s[t - off] : 0;
        __syncthreads();
        s[t] += v;
        __syncthreads();
    }
    g_scan[gid] = s[t];
    if (t == 1023) g_bsum[blockIdx.x] = s[t];
}

__global__ void k_scan2() {
    __shared__ int s[64];
    int t = threadIdx.x;
    s[t] = g_bsum[t];
    __syncthreads();
    for (int off = 1; off < 64; off <<= 1) {
        int v = (t >= off) ? s[t - off] : 0;
        __syncthreads();
        s[t] += v;
        __syncthreads();
    }
    g_boff[t] = s[t] - g_bsum[t];
}

__global__ void k_scan3() {
    int i = blockIdx.x * blockDim.x + threadIdx.x;
    if (i >= NN) return;
    int excl = g_scan[i] - g_deg[i] + g_boff[i >> 10];
    g_rowptr[i] = excl;
    g_cursor[i] = excl;
    g_dinv[i] = rsqrtf((float)g_deg[i] + 1.0f);
    if (i == 0) g_rowptr[NN] = NE;
}

__global__ void k_fill(const int* __restrict__ w) {
    int i = blockIdx.x * blockDim.x + threadIdx.x;
    if (i >= NE) return;
    int s, d;
    if (g_is64) { s = w[2 * i]; d = w[2 * (NE + i)]; }
    else        { s = w[i];     d = w[NE + i]; }
    int p = atomicAdd(&g_cursor[d & (NN - 1)], 1);
    g_col[p] = s & (NN - 1);
}

// ---------------- W1 fp16 transpose + tile-counter reset ----------------
__global__ void k_wconv(const float* __restrict__ W1) {
    int i = blockIdx.x * blockDim.x + threadIdx.x;  // i = k*64+n
    if (i == 0) g_tile = 0;
    if (i >= DIN * DH) return;
    int k = i >> 6, n = i & 63;
    g_w1h[n * DIN + k] = __float2half_rn(W1[i]);
}

// ---------------- GEMM1 (HMMA fp16 split 2-pass, persistent) ----------------
// tile M=128 x N=64, K-chunk 32; 8 warps: 4(m) x 2(n); per warp 2 m16 x 4 n8.
// passes: Ahi*W + Alo*W  (A split exact; only W carries fp16 rounding ~2^-12)
#define SAS 40  // smem row stride (halfs): conflict-free frag loads

__device__ __forceinline__ void mma16816(float* d, const unsigned* a, const unsigned* b) {
    asm("mma.sync.aligned.m16n8k16.row.col.f32.f16.f16.f32 "
        "{%0,%1,%2,%3}, {%4,%5,%6,%7}, {%8,%9}, {%0,%1,%2,%3};"
        : "+f"(d[0]), "+f"(d[1]), "+f"(d[2]), "+f"(d[3])
        : "r"(a[0]), "r"(a[1]), "r"(a[2]), "r"(a[3]), "r"(b[0]), "r"(b[1]));
}

#define NTILES (NN / 128)

__global__ __launch_bounds__(256, 2) void k_gemm1t(const float* __restrict__ A) {
    __shared__ __half Ah[128][SAS], Al[128][SAS], Bh[64][SAS];
    __shared__ int s_tile;

    int tid = threadIdx.x;
    int wid = tid >> 5, lane = tid & 31;
    int wm = wid >> 1, wn = wid & 1;
    int g = lane >> 2, t = lane & 3;
    const unsigned* w1h32 = (const unsigned*)g_w1h;

    for (;;) {
        if (tid == 0) s_tile = atomicAdd(&g_tile, 1);
        __syncthreads();
        int tile = s_tile;
        if (tile >= NTILES) break;
        int blockRow = tile * 128;

        float acc[2][4][4];
#pragma unroll
        for (int mt = 0; mt < 2; mt++)
#pragma unroll
            for (int nt = 0; nt < 4; nt++)
#pragma unroll
                for (int q = 0; q < 4; q++) acc[mt][nt][q] = 0.0f;

        // prefetch chunk 0
        float4 av[4];
        unsigned bhv[4];
#pragma unroll
        for (int i = 0; i < 4; i++) {
            int f = tid + i * 256;
            int row = f >> 3, kq = (f & 7) * 4;
            av[i] = *(const float4*)(A + (size_t)(blockRow + row) * DIN + kq);
            int br = f >> 4, bc = f & 15;
            bhv[i] = w1h32[br * (DIN / 2) + bc];
        }

        for (int kt = 0; kt < DIN; kt += 32) {
            // stage current chunk (convert A fp32 -> fp16 hi/lo)
#pragma unroll
            for (int i = 0; i < 4; i++) {
                int f = tid + i * 256;
                int row = f >> 3, kq = (f & 7) * 4;
                float4 v = av[i];
                __half2 h01 = __float22half2_rn(make_float2(v.x, v.y));
                __half2 h23 = __float22half2_rn(make_float2(v.z, v.w));
                float rx = v.x - __half2float(__low2half(h01));
                float ry = v.y - __half2float(__high2half(h01));
                float rz = v.z - __half2float(__low2half(h23));
                float rw = v.w - __half2float(__high2half(h23));
                __half2 l01 = __float22half2_rn(make_float2(rx, ry));
                __half2 l23 = __float22half2_rn(make_float2(rz, rw));
                *(unsigned*)&Ah[row][kq]     = *(unsigned*)&h01;
                *(unsigned*)&Ah[row][kq + 2] = *(unsigned*)&h23;
                *(unsigned*)&Al[row][kq]     = *(unsigned*)&l01;
                *(unsigned*)&Al[row][kq + 2] = *(unsigned*)&l23;
                int br = f >> 4, bc = f & 15;
                *(unsigned*)&Bh[br][bc * 2] = bhv[i];
            }
            __syncthreads();

            // prefetch next chunk
            if (kt + 32 < DIN) {
#pragma unroll
                for (int i = 0; i < 4; i++) {
                    int f = tid + i * 256;
                    int row = f >> 3, kq = (f & 7) * 4;
                    av[i] = *(const float4*)(A + (size_t)(blockRow + row) * DIN + kt + 32 + kq);
                    int br = f >> 4, bc = f & 15;
                    bhv[i] = w1h32[br * (DIN / 2) + (kt + 32) / 2 + bc];
                }
            }

#pragma unroll
            for (int kk = 0; kk < 32; kk += 16) {
                unsigned ah[2][4], al[2][4], bh[4][2];
#pragma unroll
                for (int mt = 0; mt < 2; mt++) {
                    int r0 = wm * 32 + mt * 16;
                    ah[mt][0] = *(unsigned*)&Ah[r0 + g][kk + 2 * t];
                    ah[mt][1] = *(unsigned*)&Ah[r0 + g + 8][kk + 2 * t];
                    ah[mt][2] = *(unsigned*)&Ah[r0 + g][kk + 2 * t + 8];
                    ah[mt][3] = *(unsigned*)&Ah[r0 + g + 8][kk + 2 * t + 8];
                    al[mt][0] = *(unsigned*)&Al[r0 + g][kk + 2 * t];
                    al[mt][1] = *(unsigned*)&Al[r0 + g + 8][kk + 2 * t];
                    al[mt][2] = *(unsigned*)&Al[r0 + g][kk + 2 * t + 8];
                    al[mt][3] = *(unsigned*)&Al[r0 + g + 8][kk + 2 * t + 8];
                }
#pragma unroll
                for (int nt = 0; nt < 4; nt++) {
                    int c0 = wn * 32 + nt * 8;
                    bh[nt][0] = *(unsigned*)&Bh[c0 + g][kk + 2 * t];
                    bh[nt][1] = *(unsigned*)&Bh[c0 + g][kk + 2 * t + 8];
                }
#pragma unroll
                for (int mt = 0; mt < 2; mt++)
#pragma unroll
                    for (int nt = 0; nt < 4; nt++) {
                        mma16816(acc[mt][nt], ah[mt], bh[nt]);
                        mma16816(acc[mt][nt], al[mt], bh[nt]);
                    }
            }
            __syncthreads();
        }

        // epilogue: scale by dinv[row], store
#pragma unroll
        for (int mt = 0; mt < 2; mt++) {
            int r0 = blockRow + wm * 32 + mt * 16 + g;
            int r1 = r0 + 8;
            float d0 = g_dinv[r0], d1 = g_dinv[r1];
#pragma unroll
            for (int nt = 0; nt < 4; nt++) {
                int c = wn * 32 + nt * 8 + 2 * t;
                g_y1[(size_t)r0 * DH + c]     = acc[mt][nt][0] * d0;
                g_y1[(size_t)r0 * DH + c + 1] = acc[mt][nt][1] * d0;
                g_y1[(size_t)r1 * DH + c]     = acc[mt][nt][2] * d1;
                g_y1[(size_t)r1 * DH + c + 1] = acc[mt][nt][3] * d1;
            }
        }
        __syncthreads();
    }
}

// ---------------- layer-1 aggregation + bias + relu (warp per node, float2) ----------------
__global__ __launch_bounds__(256) void k_agg1(const float* __restrict__ b1) {
    int warp = (blockIdx.x * blockDim.x + threadIdx.x) >> 5;
    int lane = threadIdx.x & 31;
    if (warp >= NN) return;
    const float2* y2p = (const float2*)g_y1;
    float2 a = y2p[(size_t)warp * 32 + lane];
    int e = g_rowptr[warp], e1 = g_rowptr[warp + 1];
    for (; e + 4 <= e1; e += 4) {
        int s0 = g_col[e], s1 = g_col[e + 1], s2 = g_col[e + 2], s3 = g_col[e + 3];
        float2 v0 = y2p[(size_t)s0 * 32 + lane];
        float2 v1 = y2p[(size_t)s1 * 32 + lane];
        float2 v2 = y2p[(size_t)s2 * 32 + lane];
        float2 v3 = y2p[(size_t)s3 * 32 + lane];
        a.x += (v0.x + v1.x) + (v2.x + v3.x);
        a.y += (v0.y + v1.y) + (v2.y + v3.y);
    }
    for (; e < e1; e++) {
        float2 v = y2p[(size_t)g_col[e] * 32 + lane];
        a.x += v.x; a.y += v.y;
    }
    float dv = g_dinv[warp];
    float2 bb = ((const float2*)b1)[lane];
    float2 o = make_float2(fmaxf(fmaf(dv, a.x, bb.x), 0.0f),
                           fmaxf(fmaf(dv, a.y, bb.y), 0.0f));
    ((float2*)g_h)[(size_t)warp * 32 + lane] = o;
}

// ---------------- GEMM2: y2 = dinv * (h @ W2)  (warp per node) ----------------
__global__ __launch_bounds__(256) void k_gemm2(const float* __restrict__ W2) {
    __shared__ float Ws[DH * NC];
    for (int i = threadIdx.x; i < DH * NC; i += 256) Ws[i] = W2[i];
    __syncthreads();
    int warp = (blockIdx.x * blockDim.x + threadIdx.x) >> 5;
    int lane = threadIdx.x & 31;
    if (warp >= NN) return;
    const float* hr = g_h + (size_t)warp * DH;
    float acc = 0.0f;
#pragma unroll
    for (int k = 0; k < DH; k += 4) {
        float4 hv = *(const float4*)(hr + k);
        acc = fmaf(hv.x, Ws[(k + 0) * NC + lane], acc);
        acc = fmaf(hv.y, Ws[(k + 1) * NC + lane], acc);
        acc = fmaf(hv.z, Ws[(k + 2) * NC + lane], acc);
        acc = fmaf(hv.w, Ws[(k + 3) * NC + lane], acc);
    }
    g_y2[(size_t)warp * NC + lane] = acc * g_dinv[warp];
}

// ---------------- layer-2 aggregation + bias + log_softmax ----------------
__global__ __launch_bounds__(256) void k_agg2(const float* __restrict__ b2,
                                              float* __restrict__ out) {
    int warp = (blockIdx.x * blockDim.x + threadIdx.x) >> 5;
    int lane = threadIdx.x & 31;
    if (warp >= NN) return;
    float a = g_y2[(size_t)warp * NC + lane];
    int e = g_rowptr[warp], e1 = g_rowptr[warp + 1];
    for (; e + 4 <= e1; e += 4) {
        int s0 = g_col[e], s1 = g_col[e + 1], s2 = g_col[e + 2], s3 = g_col[e + 3];
        float v0 = g_y2[(size_t)s0 * NC + lane];
        float v1 = g_y2[(size_t)s1 * NC + lane];
        float v2 = g_y2[(size_t)s2 * NC + lane];
        float v3 = g_y2[(size_t)s3 * NC + lane];
        a += (v0 + v1) + (v2 + v3);
    }
    for (; e < e1; e++) a += g_y2[(size_t)g_col[e] * NC + lane];

    float v = fmaf(g_dinv[warp], a, b2[lane]);
    float mx = v;
#pragma unroll
    for (int o = 16; o; o >>= 1) mx = fmaxf(mx, __shfl_xor_sync(0xffffffffu, mx, o));
    float ex = __expf(v - mx);
    float sm = ex;
#pragma unroll
    for (int o = 16; o; o >>= 1) sm += __shfl_xor_sync(0xffffffffu, sm, o);
    out[(size_t)warp * NC + lane] = v - mx - logf(sm);
}

// ---------------- launch ----------------
extern "C" void kernel_launch(void* const* d_in, const int* in_sizes, int n_in,
                              void* d_out, int out_size) {
    const float* x  = (const float*)d_in[0];
    const int*   ei = (const int*)d_in[1];
    const float* W1 = (const float*)d_in[2];
    const float* b1 = (const float*)d_in[3];
    const float* W2 = (const float*)d_in[4];
    const float* b2 = (const float*)d_in[5];
    float* out = (float*)d_out;

    k_detect<<<1, 1024>>>(ei);
    k_prep  <<<NE / 256, 256>>>(ei);
    k_scan1 <<<64, 1024>>>();
    k_scan2 <<<1, 64>>>();
    k_scan3 <<<NN / 256, 256>>>();
    k_fill  <<<NE / 256, 256>>>(ei);
    k_wconv <<<(DIN * DH + 255) / 256, 256>>>(W1);
    k_gemm1t<<<296, 256>>>(x);
    k_agg1  <<<NN / 8, 256>>>(b1);
    k_gemm2 <<<NN / 8, 256>>>(W2);
    k_agg2  <<<NN / 8, 256>>>(b2, out);
}

// round 6
// speedup vs baseline: 1.8405x; 1.0998x over previous
#include <cuda_runtime.h>
#include <cuda_fp16.h>

#define NN 65536
#define NE 1048576
#define DIN 1024
#define DH 64
#define NC 32

// ---------------- scratch (static device globals; no allocs) ----------------
__device__ int     g_is64;
__device__ int     g_tile;
__device__ int     g_deg[NN];
__device__ int     g_scan[NN];
__device__ int     g_bsum[64];
__device__ int     g_boff[64];
__device__ int     g_rowptr[NN + 1];
__device__ int     g_cursor[NN];
__device__ int     g_col[NE];
__device__ float   g_dinv[NN];
__device__ __half2 g_y1h[(size_t)NN * 32];   // y1 = dinv*(x@W1), fp16 pairs
__device__ float   g_y2[(size_t)NN * NC];
__device__ __half  g_w1h[DH * DIN];          // W1^T fp16: [n][k]

// ---------------- dtype detect + zero deg ----------------
__global__ void k_detect(const int* __restrict__ w) {
    __shared__ int s[1024];
    int t = threadIdx.x;
    int acc = 0;
    for (int i = t; i < 65536; i += 1024) acc |= w[2 * i + 1];
    s[t] = acc;
    for (int i = t; i < NN; i += 1024) g_deg[i] = 0;
    __syncthreads();
    for (int off = 512; off; off >>= 1) {
        if (t < off) s[t] |= s[t + off];
        __syncthreads();
    }
    if (t == 0) g_is64 = (s[0] == 0) ? 1 : 0;
}

__global__ void k_prep(const int* __restrict__ w) {
    int i = blockIdx.x * blockDim.x + threadIdx.x;
    if (i >= NE) return;
    int d = g_is64 ? w[2 * (NE + i)] : w[NE + i];
    atomicAdd(&g_deg[d & (NN - 1)], 1);
}

__global__ void k_scan1() {
    __shared__ int s[1024];
    int t = threadIdx.x;
    int gid = blockIdx.x * 1024 + t;
    s[t] = g_deg[gid];
    __syncthreads();
    for (int off = 1; off < 1024; off <<= 1) {
        int v = (t >= off) ? s[t - off] : 0;
        __syncthreads();
        s[t] += v;
        __syncthreads();
    }
    g_scan[gid] = s[t];
    if (t == 1023) g_bsum[blockIdx.x] = s[t];
}

__global__ void k_scan2() {
    __shared__ int s[64];
    int t = threadIdx.x;
    s[t] = g_bsum[t];
    __syncthreads();
    for (int off = 1; off < 64; off <<= 1) {
        int v = (t >= off) ? s[t - off] : 0;
        __syncthreads();
        s[t] += v;
        __syncthreads();
    }
    g_boff[t] = s[t] - g_bsum[t];
}

__global__ void k_scan3() {
    int i = blockIdx.x * blockDim.x + threadIdx.x;
    if (i >= NN) return;
    int excl = g_scan[i] - g_deg[i] + g_boff[i >> 10];
    g_rowptr[i] = excl;
    g_cursor[i] = excl;
    g_dinv[i] = rsqrtf((float)g_deg[i] + 1.0f);
    if (i == 0) g_rowptr[NN] = NE;
}

__global__ void k_fill(const int* __restrict__ w) {
    int i = blockIdx.x * blockDim.x + threadIdx.x;
    if (i >= NE) return;
    int s, d;
    if (g_is64) { s = w[2 * i]; d = w[2 * (NE + i)]; }
    else        { s = w[i];     d = w[NE + i]; }
    int p = atomicAdd(&g_cursor[d & (NN - 1)], 1);
    g_col[p] = s & (NN - 1);
}

// ---------------- W1 fp16 transpose + tile-counter reset ----------------
__global__ void k_wconv(const float* __restrict__ W1) {
    int i = blockIdx.x * blockDim.x + threadIdx.x;  // i = k*64+n
    if (i == 0) g_tile = 0;
    if (i >= DIN * DH) return;
    int k = i >> 6, n = i & 63;
    g_w1h[n * DIN + k] = __float2half_rn(W1[i]);
}

// ---------------- GEMM1 (HMMA fp16 single pass, persistent) ----------------
// tile M=128 x N=64, K-chunk 32; 8 warps: 4(m) x 2(n); per warp 2 m16 x 4 n8.
#define SAS 40

__device__ __forceinline__ void mma16816(float* d, const unsigned* a, const unsigned* b) {
    asm("mma.sync.aligned.m16n8k16.row.col.f32.f16.f16.f32 "
        "{%0,%1,%2,%3}, {%4,%5,%6,%7}, {%8,%9}, {%0,%1,%2,%3};"
        : "+f"(d[0]), "+f"(d[1]), "+f"(d[2]), "+f"(d[3])
        : "r"(a[0]), "r"(a[1]), "r"(a[2]), "r"(a[3]), "r"(b[0]), "r"(b[1]));
}

#define NTILES (NN / 128)

__global__ __launch_bounds__(256, 2) void k_gemm1t(const float* __restrict__ A) {
    __shared__ __half Ah[128][SAS], Bh[64][SAS];
    __shared__ int s_tile;

    int tid = threadIdx.x;
    int wid = tid >> 5, lane = tid & 31;
    int wm = wid >> 1, wn = wid & 1;
    int g = lane >> 2, t = lane & 3;
    const unsigned* w1h32 = (const unsigned*)g_w1h;

    for (;;) {
        if (tid == 0) s_tile = atomicAdd(&g_tile, 1);
        __syncthreads();
        int tile = s_tile;
        if (tile >= NTILES) break;
        int blockRow = tile * 128;

        float acc[2][4][4];
#pragma unroll
        for (int mt = 0; mt < 2; mt++)
#pragma unroll
            for (int nt = 0; nt < 4; nt++)
#pragma unroll
                for (int q = 0; q < 4; q++) acc[mt][nt][q] = 0.0f;

        float4 av[4];
        unsigned bhv[4];
#pragma unroll
        for (int i = 0; i < 4; i++) {
            int f = tid + i * 256;
            int row = f >> 3, kq = (f & 7) * 4;
            av[i] = *(const float4*)(A + (size_t)(blockRow + row) * DIN + kq);
            int br = f >> 4, bc = f & 15;
            bhv[i] = w1h32[br * (DIN / 2) + bc];
        }

        for (int kt = 0; kt < DIN; kt += 32) {
#pragma unroll
            for (int i = 0; i < 4; i++) {
                int f = tid + i * 256;
                int row = f >> 3, kq = (f & 7) * 4;
                float4 v = av[i];
                __half2 h01 = __float22half2_rn(make_float2(v.x, v.y));
                __half2 h23 = __float22half2_rn(make_float2(v.z, v.w));
                *(unsigned*)&Ah[row][kq]     = *(unsigned*)&h01;
                *(unsigned*)&Ah[row][kq + 2] = *(unsigned*)&h23;
                int br = f >> 4, bc = f & 15;
                *(unsigned*)&Bh[br][bc * 2] = bhv[i];
            }
            __syncthreads();

            if (kt + 32 < DIN) {
#pragma unroll
                for (int i = 0; i < 4; i++) {
                    int f = tid + i * 256;
                    int row = f >> 3, kq = (f & 7) * 4;
                    av[i] = *(const float4*)(A + (size_t)(blockRow + row) * DIN + kt + 32 + kq);
                    int br = f >> 4, bc = f & 15;
                    bhv[i] = w1h32[br * (DIN / 2) + (kt + 32) / 2 + bc];
                }
            }

#pragma unroll
            for (int kk = 0; kk < 32; kk += 16) {
                unsigned ah[2][4], bh[4][2];
#pragma unroll
                for (int mt = 0; mt < 2; mt++) {
                    int r0 = wm * 32 + mt * 16;
                    ah[mt][0] = *(unsigned*)&Ah[r0 + g][kk + 2 * t];
                    ah[mt][1] = *(unsigned*)&Ah[r0 + g + 8][kk + 2 * t];
                    ah[mt][2] = *(unsigned*)&Ah[r0 + g][kk + 2 * t + 8];
                    ah[mt][3] = *(unsigned*)&Ah[r0 + g + 8][kk + 2 * t + 8];
                }
#pragma unroll
                for (int nt = 0; nt < 4; nt++) {
                    int c0 = wn * 32 + nt * 8;
                    bh[nt][0] = *(unsigned*)&Bh[c0 + g][kk + 2 * t];
                    bh[nt][1] = *(unsigned*)&Bh[c0 + g][kk + 2 * t + 8];
                }
#pragma unroll
                for (int mt = 0; mt < 2; mt++)
#pragma unroll
                    for (int nt = 0; nt < 4; nt++)
                        mma16816(acc[mt][nt], ah[mt], bh[nt]);
            }
            __syncthreads();
        }

        // epilogue: scale by dinv, store as half2
#pragma unroll
        for (int mt = 0; mt < 2; mt++) {
            int r0 = blockRow + wm * 32 + mt * 16 + g;
            int r1 = r0 + 8;
            float d0 = g_dinv[r0], d1 = g_dinv[r1];
#pragma unroll
            for (int nt = 0; nt < 4; nt++) {
                int ci = wn * 16 + nt * 4 + t;  // half2 index (col pair)
                g_y1h[(size_t)r0 * 32 + ci] =
                    __floats2half2_rn(acc[mt][nt][0] * d0, acc[mt][nt][1] * d0);
                g_y1h[(size_t)r1 * 32 + ci] =
                    __floats2half2_rn(acc[mt][nt][2] * d1, acc[mt][nt][3] * d1);
            }
        }
        __syncthreads();
    }
}

// ---------------- layer-1 aggregation + relu + GEMM2 fused (warp per node) ----------------
__global__ __launch_bounds__(256) void k_agg1g2(const float* __restrict__ b1,
                                                const float* __restrict__ W2) {
    __shared__ float Ws[DH * NC];
    for (int i = threadIdx.x; i < DH * NC; i += 256) Ws[i] = W2[i];
    __syncthreads();

    int warp = (blockIdx.x * blockDim.x + threadIdx.x) >> 5;
    int lane = threadIdx.x & 31;
    if (warp >= NN) return;

    const __half2* yp = g_y1h;
    float2 a = __half22float2(yp[(size_t)warp * 32 + lane]);
    int e = g_rowptr[warp], e1 = g_rowptr[warp + 1];
    for (; e + 4 <= e1; e += 4) {
        int s0 = g_col[e], s1 = g_col[e + 1], s2 = g_col[e + 2], s3 = g_col[e + 3];
        float2 v0 = __half22float2(yp[(size_t)s0 * 32 + lane]);
        float2 v1 = __half22float2(yp[(size_t)s1 * 32 + lane]);
        float2 v2 = __half22float2(yp[(size_t)s2 * 32 + lane]);
        float2 v3 = __half22float2(yp[(size_t)s3 * 32 + lane]);
        a.x += (v0.x + v1.x) + (v2.x + v3.x);
        a.y += (v0.y + v1.y) + (v2.y + v3.y);
    }
    for (; e < e1; e++) {
        float2 v = __half22float2(yp[(size_t)g_col[e] * 32 + lane]);
        a.x += v.x; a.y += v.y;
    }

    float dv = g_dinv[warp];
    float2 bb = ((const float2*)b1)[lane];
    float hx = fmaxf(fmaf(dv, a.x, bb.x), 0.0f);   // h[2*lane]
    float hy = fmaxf(fmaf(dv, a.y, bb.y), 0.0f);   // h[2*lane+1]

    // fused GEMM2: y2[c] = dinv * sum_k h[k]*W2[k][c], c = lane
    float acc2 = 0.0f;
#pragma unroll
    for (int k2 = 0; k2 < 32; k2++) {
        float sx = __shfl_sync(0xffffffffu, hx, k2);
        float sy = __shfl_sync(0xffffffffu, hy, k2);
        acc2 = fmaf(sx, Ws[(2 * k2) * NC + lane], acc2);
        acc2 = fmaf(sy, Ws[(2 * k2 + 1) * NC + lane], acc2);
    }
    g_y2[(size_t)warp * NC + lane] = acc2 * dv;
}

// ---------------- layer-2 aggregation + bias + log_softmax ----------------
__global__ __launch_bounds__(256) void k_agg2(const float* __restrict__ b2,
                                              float* __restrict__ out) {
    int warp = (blockIdx.x * blockDim.x + threadIdx.x) >> 5;
    int lane = threadIdx.x & 31;
    if (warp >= NN) return;
    float a = g_y2[(size_t)warp * NC + lane];
    int e = g_rowptr[warp], e1 = g_rowptr[warp + 1];
    for (; e + 4 <= e1; e += 4) {
        int s0 = g_col[e], s1 = g_col[e + 1], s2 = g_col[e + 2], s3 = g_col[e + 3];
        float v0 = g_y2[(size_t)s0 * NC + lane];
        float v1 = g_y2[(size_t)s1 * NC + lane];
        float v2 = g_y2[(size_t)s2 * NC + lane];
        float v3 = g_y2[(size_t)s3 * NC + lane];
        a += (v0 + v1) + (v2 + v3);
    }
    for (; e < e1; e++) a += g_y2[(size_t)g_col[e] * NC + lane];

    float v = fmaf(g_dinv[warp], a, b2[lane]);
    float mx = v;
#pragma unroll
    for (int o = 16; o; o >>= 1) mx = fmaxf(mx, __shfl_xor_sync(0xffffffffu, mx, o));
    float ex = __expf(v - mx);
    float sm = ex;
#pragma unroll
    for (int o = 16; o; o >>= 1) sm += __shfl_xor_sync(0xffffffffu, sm, o);
    out[(size_t)warp * NC + lane] = v - mx - logf(sm);
}

// ---------------- launch ----------------
extern "C" void kernel_launch(void* const* d_in, const int* in_sizes, int n_in,
                              void* d_out, int out_size) {
    const float* x  = (const float*)d_in[0];
    const int*   ei = (const int*)d_in[1];
    const float* W1 = (const float*)d_in[2];
    const float* b1 = (const float*)d_in[3];
    const float* W2 = (const float*)d_in[4];
    const float* b2 = (const float*)d_in[5];
    float* out = (float*)d_out;

    k_detect<<<1, 1024>>>(ei);
    k_prep  <<<NE / 256, 256>>>(ei);
    k_scan1 <<<64, 1024>>>();
    k_scan2 <<<1, 64>>>();
    k_scan3 <<<NN / 256, 256>>>();
    k_fill  <<<NE / 256, 256>>>(ei);
    k_wconv <<<(DIN * DH + 255) / 256, 256>>>(W1);
    k_gemm1t<<<296, 256>>>(x);
    k_agg1g2<<<NN / 8, 256>>>(b1, W2);
    k_agg2  <<<NN / 8, 256>>>(b2, out);
}